// round 5
// baseline (speedup 1.0000x reference)
#include <cuda_runtime.h>
#include <cstdint>
#include <cstddef>

#define BB   64
#define TDEC 400
#define TENC 512
#define DD   256
#define PRE  128
#define ODIM 400
#define CIN  (PRE + DD)   // 384
#define GRID 128
#define NTH  256

// ---------------- scratch (device globals; no allocation allowed) ----------
__device__ float g_pre1[BB * TDEC * DD];     // prenet layer-1 out  (26.2 MB)
__device__ float g_p[BB * TDEC * PRE];       // prenet out          (13.1 MB)
__device__ float g_keys[BB * TENC * DD];     // memory @ Wm         (33.5 MB)
__device__ float g_k0T[3 * DD * CIN];
__device__ float g_r0T[3 * DD * DD];
__device__ float g_k1T[3 * DD * DD];
__device__ float g_r1T[3 * DD * DD];
__device__ float g_WqT[DD * DD];
__device__ float g_WaT[DD * 2 * DD];
__device__ float g_WoT[ODIM * DD];
__device__ float g_h0[2][BB * DD];
__device__ float g_h1[2][BB * DD];
__device__ float g_att[2][BB * DD];
__device__ float g_ctxpart[BB * 2 * DD];
__device__ float g_ml[BB * 2 * 2];           // (m, l) per (b, half)
__device__ unsigned g_barArrive;
__device__ unsigned g_barRelease;
__device__ unsigned g_pairCnt[BB];

// ---------------- small helpers -------------------------------------------
__device__ __forceinline__ float warp_sum_f(float v) {
#pragma unroll
    for (int o = 16; o; o >>= 1) v += __shfl_xor_sync(0xffffffffu, v, o);
    return v;
}
__device__ __forceinline__ float sigm_f(float x) {
    return 1.0f / (1.0f + __expf(-x));
}
// accurate-and-fast tanh: 1 - 2/(e^{2x}+1); __expf/__fdividef err ~2ulp
__device__ __forceinline__ float tanh_f(float x) {
    float e = __expf(2.0f * x);
    return 1.0f - __fdividef(2.0f, e + 1.0f);
}

__device__ __forceinline__ void grid_sync(unsigned epoch) {
    __syncthreads();
    if (threadIdx.x == 0) {
        __threadfence();
        unsigned arrived = atomicAdd(&g_barArrive, 1u) + 1u;
        if (arrived == epoch * gridDim.x) {
            *(volatile unsigned*)&g_barRelease = epoch;
            __threadfence();
        } else {
            while (*(volatile unsigned*)&g_barRelease < epoch) { }
            __threadfence();
        }
    }
    __syncthreads();
}

// ---------------- init ------------------------------------------------------
__global__ void dec_init_kernel() {
    int tid = blockIdx.x * blockDim.x + threadIdx.x;
    if (tid == 0) { g_barArrive = 0; g_barRelease = 0; }
    if (tid < BB) g_pairCnt[tid] = 0;
    for (int i = tid; i < BB * DD; i += gridDim.x * blockDim.x) {
        g_h0[0][i] = 0.f; g_h1[0][i] = 0.f; g_att[0][i] = 0.f;
    }
}

// ---------------- transpose [R,C] -> [C,R] ---------------------------------
__global__ void dec_transpose_kernel(const float* __restrict__ src,
                                     float* __restrict__ dst, int R, int C) {
    int idx = blockIdx.x * blockDim.x + threadIdx.x;
    if (idx < R * C) {
        int r = idx / C, c = idx - r * C;
        dst[c * R + r] = src[idx];
    }
}

// ---------------- fp32 SGEMM 128x128x8, TM=TN=8 ----------------------------
// C[M,N] = op(A[M,K] @ B[K,N] + bias), all row-major, dims multiples of tile
__global__ __launch_bounds__(256) void dec_sgemm_kernel(
    const float* __restrict__ A, const float* __restrict__ Bm,
    const float* __restrict__ bias, float* __restrict__ C,
    int M, int N, int K, int relu)
{
    __shared__ float As[8][128];
    __shared__ float Bs[8][128];
    const int tid = threadIdx.x;
    const int m0 = blockIdx.y * 128;
    const int n0 = blockIdx.x * 128;
    const int ty = tid / 16;          // 0..15
    const int txx = tid & 15;         // 0..15
    const int arow = tid >> 1;        // 0..127
    const int acol = (tid & 1) * 4;   // 0 or 4
    const int brow = tid >> 5;        // 0..7
    const int bcol = (tid & 31) * 4;
    float acc[8][8];
#pragma unroll
    for (int i = 0; i < 8; ++i)
#pragma unroll
        for (int j = 0; j < 8; ++j) acc[i][j] = 0.f;

    for (int k0 = 0; k0 < K; k0 += 8) {
        float4 a4 = *reinterpret_cast<const float4*>(
            &A[(size_t)(m0 + arow) * K + k0 + acol]);
        As[acol + 0][arow] = a4.x; As[acol + 1][arow] = a4.y;
        As[acol + 2][arow] = a4.z; As[acol + 3][arow] = a4.w;
        float4 b4 = *reinterpret_cast<const float4*>(
            &Bm[(size_t)(k0 + brow) * N + n0 + bcol]);
        *reinterpret_cast<float4*>(&Bs[brow][bcol]) = b4;
        __syncthreads();
#pragma unroll
        for (int k = 0; k < 8; ++k) {
            float af[8], bf[8];
#pragma unroll
            for (int i = 0; i < 8; ++i) af[i] = As[k][ty * 8 + i];
#pragma unroll
            for (int j = 0; j < 8; ++j) bf[j] = Bs[k][txx * 8 + j];
#pragma unroll
            for (int i = 0; i < 8; ++i)
#pragma unroll
                for (int j = 0; j < 8; ++j) acc[i][j] = fmaf(af[i], bf[j], acc[i][j]);
        }
        __syncthreads();
    }
#pragma unroll
    for (int i = 0; i < 8; ++i) {
        int m = m0 + ty * 8 + i;
#pragma unroll
        for (int j = 0; j < 8; ++j) {
            int n = n0 + txx * 8 + j;
            float c = acc[i][j] + (bias ? bias[n] : 0.f);
            if (relu) c = fmaxf(c, 0.f);
            C[(size_t)m * N + n] = c;
        }
    }
}

// ---------------- persistent decoder ---------------------------------------
__global__ __launch_bounds__(NTH) void dec_main_kernel(
    const float* __restrict__ memory,
    const float* __restrict__ bi0, const float* __restrict__ br0,
    const float* __restrict__ bi1, const float* __restrict__ br1,
    const float* __restrict__ v,   const float* __restrict__ bo,
    float* __restrict__ out)
{
    const int cta  = blockIdx.x;
    const int tid  = threadIdx.x;
    const int warp = tid >> 5, lane = tid & 31;
    const int gwarp = cta * 8 + warp;       // 0..1023
    unsigned ep = 0;

    __shared__ float s_q[DD];
    __shared__ float s_sc[256];
    __shared__ float s_v[DD];
    __shared__ float s_red[8];

    for (int i = tid; i < DD; i += NTH) s_v[i] = v[i];
    __syncthreads();

    for (int step = 0; step < TDEC; ++step) {
        const int par = step & 1;
        const float* h0c  = g_h0[par];    float* h0n  = g_h0[par ^ 1];
        const float* h1c  = g_h1[par];    float* h1n  = g_h1[par ^ 1];
        const float* attc = g_att[par];   float* attn_ = g_att[par ^ 1];

        // ============ P1: GRU0  (+ output dense y for step-1) ==============
        {
            const int obase = gwarp * 16;
            for (int oi = 0; oi < 16; ++oi) {
                int o = obase + oi;
                int b = o >> 8, d = o & 255;
                const float* pb = &g_p[(b * TDEC + step) * PRE];
                const float* ab = &attc[b * DD];
                const float* hb = &h0c[b * DD];
                const float* kz = &g_k0T[d * CIN];
                const float* kr = &g_k0T[(DD + d) * CIN];
                const float* kh = &g_k0T[(2 * DD + d) * CIN];
                const float* rz = &g_r0T[d * DD];
                const float* rr = &g_r0T[(DD + d) * DD];
                const float* rh = &g_r0T[(2 * DD + d) * DD];
                float az = 0, ar = 0, ah = 0, gz = 0, gr = 0, gh = 0;
#pragma unroll
                for (int i = lane; i < PRE; i += 32) {
                    float x = pb[i];
                    az = fmaf(x, kz[i], az); ar = fmaf(x, kr[i], ar); ah = fmaf(x, kh[i], ah);
                }
#pragma unroll
                for (int i2 = lane; i2 < DD; i2 += 32) {
                    float x = ab[i2]; int i = PRE + i2;
                    az = fmaf(x, kz[i], az); ar = fmaf(x, kr[i], ar); ah = fmaf(x, kh[i], ah);
                    float h = hb[i2];
                    gz = fmaf(h, rz[i2], gz); gr = fmaf(h, rr[i2], gr); gh = fmaf(h, rh[i2], gh);
                }
#pragma unroll
                for (int off = 16; off; off >>= 1) {
                    az += __shfl_xor_sync(0xffffffffu, az, off);
                    ar += __shfl_xor_sync(0xffffffffu, ar, off);
                    ah += __shfl_xor_sync(0xffffffffu, ah, off);
                    gz += __shfl_xor_sync(0xffffffffu, gz, off);
                    gr += __shfl_xor_sync(0xffffffffu, gr, off);
                    gh += __shfl_xor_sync(0xffffffffu, gh, off);
                }
                if (lane == 0) {
                    float z = sigm_f(az + gz + bi0[d] + br0[d]);
                    float r = sigm_f(ar + gr + bi0[DD + d] + br0[DD + d]);
                    float hc = tanh_f(ah + bi0[2 * DD + d] + r * (gh + br0[2 * DD + d]));
                    h0n[b * DD + d] = z * hb[d] + (1.0f - z) * hc;
                }
            }
            if (step > 0) {
                const int ybase = gwarp * 25;
                for (int o = ybase; o < ybase + 25; ++o) {
                    int b = o / ODIM, j = o - b * ODIM;
                    const float* wrow = &g_WoT[j * DD];
                    const float* arow2 = &attc[b * DD];
                    float acc = 0;
#pragma unroll
                    for (int i = lane; i < DD; i += 32) acc = fmaf(arow2[i], wrow[i], acc);
                    acc = warp_sum_f(acc);
                    if (lane == 0)
                        out[(size_t)(b * TDEC + (step - 1)) * ODIM + j] = acc + bo[j];
                }
            }
        }
        grid_sync(++ep);

        // ============ P2: GRU1 ==============================================
        {
            const int obase = gwarp * 16;
            for (int oi = 0; oi < 16; ++oi) {
                int o = obase + oi;
                int b = o >> 8, d = o & 255;
                const float* xb = &h0n[b * DD];
                const float* hb = &h1c[b * DD];
                const float* kz = &g_k1T[d * DD];
                const float* kr = &g_k1T[(DD + d) * DD];
                const float* kh = &g_k1T[(2 * DD + d) * DD];
                const float* rz = &g_r1T[d * DD];
                const float* rr = &g_r1T[(DD + d) * DD];
                const float* rh = &g_r1T[(2 * DD + d) * DD];
                float az = 0, ar = 0, ah = 0, gz = 0, gr = 0, gh = 0;
#pragma unroll
                for (int i = lane; i < DD; i += 32) {
                    float x = xb[i], h = hb[i];
                    az = fmaf(x, kz[i], az); ar = fmaf(x, kr[i], ar); ah = fmaf(x, kh[i], ah);
                    gz = fmaf(h, rz[i], gz); gr = fmaf(h, rr[i], gr); gh = fmaf(h, rh[i], gh);
                }
#pragma unroll
                for (int off = 16; off; off >>= 1) {
                    az += __shfl_xor_sync(0xffffffffu, az, off);
                    ar += __shfl_xor_sync(0xffffffffu, ar, off);
                    ah += __shfl_xor_sync(0xffffffffu, ah, off);
                    gz += __shfl_xor_sync(0xffffffffu, gz, off);
                    gr += __shfl_xor_sync(0xffffffffu, gr, off);
                    gh += __shfl_xor_sync(0xffffffffu, gh, off);
                }
                if (lane == 0) {
                    float z = sigm_f(az + gz + bi1[d] + br1[d]);
                    float r = sigm_f(ar + gr + bi1[DD + d] + br1[DD + d]);
                    float hc = tanh_f(ah + bi1[2 * DD + d] + r * (gh + br1[2 * DD + d]));
                    h1n[b * DD + d] = z * hb[d] + (1.0f - z) * hc;
                }
            }
        }
        grid_sync(++ep);

        // ============ P3: query + scores + split-softmax + partial ctx ======
        {
            const int b = cta >> 1, half = cta & 1;
            // q[b,:] into smem (redundant per half; cheap)
            for (int d0 = 0; d0 < 32; ++d0) {
                int d = warp * 32 + d0;
                const float* wr = &g_WqT[d * DD];
                const float* hb = &h1n[b * DD];
                float a = 0;
#pragma unroll
                for (int i = lane; i < DD; i += 32) a = fmaf(hb[i], wr[i], a);
                a = warp_sum_f(a);
                if (lane == 0) s_q[d] = a;
            }
            __syncthreads();
            // scores for this half
            float wmax = -1e30f;
            const int tbase = half * 256;
            for (int tt = warp * 32; tt < warp * 32 + 32; ++tt) {
                const float* krow = &g_keys[(size_t)(b * TENC + tbase + tt) * DD];
                float a = 0;
#pragma unroll
                for (int k2 = 0; k2 < 8; ++k2) {
                    int d = k2 * 32 + lane;
                    a = fmaf(tanh_f(krow[d] + s_q[d]), s_v[d], a);
                }
                a = warp_sum_f(a);
                if (lane == 0) s_sc[tt] = a;
                wmax = fmaxf(wmax, a);
            }
            if (lane == 0) s_red[warp] = wmax;
            __syncthreads();
            float m_h = s_red[0];
#pragma unroll
            for (int i = 1; i < 8; ++i) m_h = fmaxf(m_h, s_red[i]);
            __syncthreads();                         // before s_red reuse
            float lw = warp_sum_f(__expf(s_sc[tid] - m_h));
            if (lane == 0) s_red[warp] = lw;
            __syncthreads();
            if (tid == 0) {
                float l_h = 0;
#pragma unroll
                for (int i = 0; i < 8; ++i) l_h += s_red[i];
                g_ml[(b * 2 + half) * 2 + 0] = m_h;
                g_ml[(b * 2 + half) * 2 + 1] = l_h;
                __threadfence();
                atomicAdd(&g_pairCnt[b], 1u);
                unsigned tgt = 2u * (unsigned)(step + 1);
                while (atomicAdd(&g_pairCnt[b], 0u) < tgt) { }
                __threadfence();
            }
            __syncthreads();
            float m0v = g_ml[(b * 2 + 0) * 2 + 0], l0v = g_ml[(b * 2 + 0) * 2 + 1];
            float m1v = g_ml[(b * 2 + 1) * 2 + 0], l1v = g_ml[(b * 2 + 1) * 2 + 1];
            float m = fmaxf(m0v, m1v);
            float l = l0v * __expf(m0v - m) + l1v * __expf(m1v - m);
            float inv_l = __fdividef(1.0f, l);
            s_sc[tid] = __expf(s_sc[tid] - m) * inv_l;   // alpha for own t
            __syncthreads();
            // partial ctx: thread = d, loop 256 t (coalesced rows)
            float acc = 0;
            const float* mb = &memory[(size_t)(b * TENC + tbase) * DD + tid];
#pragma unroll 8
            for (int t = 0; t < 256; ++t) acc = fmaf(s_sc[t], mb[(size_t)t * DD], acc);
            g_ctxpart[(b * 2 + half) * DD + tid] = acc;
        }
        grid_sync(++ep);

        // ============ P4: attention dense (Wa rows reused over 16 b) ========
        {
            const int d = gwarp & (DD - 1);
            const int bg = gwarp >> 8;                   // 0..3
            const float* wrow = &g_WaT[d * 2 * DD];
            float wreg[16];
#pragma unroll
            for (int k2 = 0; k2 < 16; ++k2) wreg[k2] = wrow[k2 * 32 + lane];
            for (int bb2 = 0; bb2 < 16; ++bb2) {
                int b = bg * 16 + bb2;
                const float* hb = &h1n[b * DD];
                const float* c0 = &g_ctxpart[(b * 2 + 0) * DD];
                const float* c1 = &g_ctxpart[(b * 2 + 1) * DD];
                float a = 0;
#pragma unroll
                for (int k2 = 0; k2 < 8; ++k2) a = fmaf(hb[k2 * 32 + lane], wreg[k2], a);
#pragma unroll
                for (int k2 = 0; k2 < 8; ++k2) {
                    int i = k2 * 32 + lane;
                    a = fmaf(c0[i] + c1[i], wreg[8 + k2], a);
                }
                a = warp_sum_f(a);
                if (lane == 0) attn_[b * DD + d] = a;
            }
        }
        grid_sync(++ep);
    }

    // final y for step 399 (attn(399) lives in g_att[0] after the last swap)
    {
        const float* attc = g_att[0];
        const int ybase = gwarp * 25;
        for (int o = ybase; o < ybase + 25; ++o) {
            int b = o / ODIM, j = o - b * ODIM;
            const float* wrow = &g_WoT[j * DD];
            const float* arow2 = &attc[b * DD];
            float acc = 0;
#pragma unroll
            for (int i = lane; i < DD; i += 32) acc = fmaf(arow2[i], wrow[i], acc);
            acc = warp_sum_f(acc);
            if (lane == 0)
                out[(size_t)(b * TDEC + (TDEC - 1)) * ODIM + j] = acc + bo[j];
        }
    }
}

// ---------------- launch ----------------------------------------------------
extern "C" void kernel_launch(void* const* d_in, const int* in_sizes, int n_in,
                              void* d_out, int out_size) {
    (void)in_sizes; (void)n_in; (void)out_size;
    const float* dec    = (const float*)d_in[0];
    const float* memory = (const float*)d_in[1];
    const float* W1  = (const float*)d_in[2];
    const float* b1  = (const float*)d_in[3];
    const float* W2  = (const float*)d_in[4];
    const float* b2  = (const float*)d_in[5];
    const float* k0  = (const float*)d_in[6];
    const float* r0  = (const float*)d_in[7];
    const float* bi0 = (const float*)d_in[8];
    const float* br0 = (const float*)d_in[9];
    const float* k1  = (const float*)d_in[10];
    const float* r1  = (const float*)d_in[11];
    const float* bi1 = (const float*)d_in[12];
    const float* br1 = (const float*)d_in[13];
    const float* Wq  = (const float*)d_in[14];
    const float* Wm  = (const float*)d_in[15];
    const float* v   = (const float*)d_in[16];
    const float* Wa  = (const float*)d_in[17];
    const float* Wo  = (const float*)d_in[18];
    const float* bo  = (const float*)d_in[19];
    float* out = (float*)d_out;

    float *pPre1, *pP, *pKeys, *pk0T, *pr0T, *pk1T, *pr1T, *pWqT, *pWaT, *pWoT;
    cudaGetSymbolAddress((void**)&pPre1, g_pre1);
    cudaGetSymbolAddress((void**)&pP,    g_p);
    cudaGetSymbolAddress((void**)&pKeys, g_keys);
    cudaGetSymbolAddress((void**)&pk0T,  g_k0T);
    cudaGetSymbolAddress((void**)&pr0T,  g_r0T);
    cudaGetSymbolAddress((void**)&pk1T,  g_k1T);
    cudaGetSymbolAddress((void**)&pr1T,  g_r1T);
    cudaGetSymbolAddress((void**)&pWqT,  g_WqT);
    cudaGetSymbolAddress((void**)&pWaT,  g_WaT);
    cudaGetSymbolAddress((void**)&pWoT,  g_WoT);

    dec_init_kernel<<<64, 256>>>();

    auto tr = [](const float* s, float* d, int R, int C) {
        dec_transpose_kernel<<<(R * C + 255) / 256, 256>>>(s, d, R, C);
    };
    tr(k0, pk0T, CIN, 3 * DD);
    tr(r0, pr0T, DD, 3 * DD);
    tr(k1, pk1T, DD, 3 * DD);
    tr(r1, pr1T, DD, 3 * DD);
    tr(Wq, pWqT, DD, DD);
    tr(Wa, pWaT, 2 * DD, DD);
    tr(Wo, pWoT, DD, ODIM);

    // prenet layer 1: [25600,400]@[400,256] +b1, relu
    dec_sgemm_kernel<<<dim3(256 / 128, (BB * TDEC) / 128), 256>>>(
        dec, W1, b1, pPre1, BB * TDEC, DD, ODIM, 1);
    // prenet layer 2: [25600,256]@[256,128] +b2, relu
    dec_sgemm_kernel<<<dim3(128 / 128, (BB * TDEC) / 128), 256>>>(
        pPre1, W2, b2, pP, BB * TDEC, PRE, DD, 1);
    // keys: [32768,256]@[256,256]
    dec_sgemm_kernel<<<dim3(256 / 128, (BB * TENC) / 128), 256>>>(
        memory, Wm, nullptr, pKeys, BB * TENC, DD, DD, 0);

    dec_main_kernel<<<GRID, NTH>>>(memory, bi0, br0, bi1, br1, v, bo, out);
}

// round 6
// speedup vs baseline: 2.7158x; 2.7158x over previous
#include <cuda_runtime.h>
#include <cstdint>
#include <cstddef>

#define BB   64
#define TDEC 400
#define TENC 512
#define DD   256
#define PRE  128
#define ODIM 400
#define CIN  (PRE + DD)   // 384
#define GRID 128
#define NTH  512

// ---------------- scratch (device globals; no allocation allowed) ----------
__device__ float g_pre1[BB * TDEC * DD];
__device__ float g_p[BB * TDEC * PRE];
__device__ float g_keys[BB * TENC * DD];
__device__ float g_k0T[3 * DD * CIN];
__device__ float g_r0T[3 * DD * DD];
__device__ float g_k1T[3 * DD * DD];
__device__ float g_r1T[3 * DD * DD];
__device__ float g_WqT[DD * DD];
__device__ float g_WaT[DD * 2 * DD];
__device__ float g_WoT[ODIM * DD];
__device__ float g_h0[2][BB * DD];
__device__ float g_h1[2][BB * DD];
__device__ float g_att[2][BB * DD];
__device__ float g_q[BB * DD];
__device__ float g_ctxpart[BB * 2 * DD];
__device__ float g_ml[BB * 2 * 2];
__device__ unsigned g_barArrive;
__device__ unsigned g_pairCnt[BB];

// ---------------- helpers ---------------------------------------------------
__device__ __forceinline__ float warp_sum_f(float v) {
#pragma unroll
    for (int o = 16; o; o >>= 1) v += __shfl_xor_sync(0xffffffffu, v, o);
    return v;
}
__device__ __forceinline__ float sigm_f(float x) {
    return 1.0f / (1.0f + __expf(-x));
}
__device__ __forceinline__ float tanh_f(float x) {
    float e = __expf(2.0f * x);
    return 1.0f - __fdividef(2.0f, e + 1.0f);
}
__device__ __forceinline__ void grid_sync(unsigned epoch) {
    __syncthreads();
    if (threadIdx.x == 0) {
        __threadfence();
        atomicAdd(&g_barArrive, 1u);
        unsigned tgt = epoch * (unsigned)GRID;
        while (*(volatile unsigned*)&g_barArrive < tgt) { }
        __threadfence();
    }
    __syncthreads();
}

// ---------------- init ------------------------------------------------------
__global__ void dec_init_kernel() {
    int tid = blockIdx.x * blockDim.x + threadIdx.x;
    if (tid == 0) g_barArrive = 0;
    if (tid < BB) g_pairCnt[tid] = 0;
    for (int i = tid; i < BB * DD; i += gridDim.x * blockDim.x) {
        g_h0[0][i] = 0.f; g_h1[0][i] = 0.f; g_att[0][i] = 0.f;
    }
}

// ---------------- transpose [R,C] -> [C,R] ----------------------------------
__global__ void dec_transpose_kernel(const float* __restrict__ src,
                                     float* __restrict__ dst, int R, int C) {
    int idx = blockIdx.x * blockDim.x + threadIdx.x;
    if (idx < R * C) {
        int r = idx / C, c = idx - r * C;
        dst[c * R + r] = src[idx];
    }
}

// ---------------- fp32 SGEMM 128x128x8, TM=TN=8 -----------------------------
__global__ __launch_bounds__(256) void dec_sgemm_kernel(
    const float* __restrict__ A, const float* __restrict__ Bm,
    const float* __restrict__ bias, float* __restrict__ C,
    int M, int N, int K, int relu)
{
    __shared__ float As[8][128];
    __shared__ float Bs[8][128];
    const int tid = threadIdx.x;
    const int m0 = blockIdx.y * 128;
    const int n0 = blockIdx.x * 128;
    const int ty = tid / 16;
    const int txx = tid & 15;
    const int arow = tid >> 1;
    const int acol = (tid & 1) * 4;
    const int brow = tid >> 5;
    const int bcol = (tid & 31) * 4;
    float acc[8][8];
#pragma unroll
    for (int i = 0; i < 8; ++i)
#pragma unroll
        for (int j = 0; j < 8; ++j) acc[i][j] = 0.f;

    for (int k0 = 0; k0 < K; k0 += 8) {
        float4 a4 = *reinterpret_cast<const float4*>(
            &A[(size_t)(m0 + arow) * K + k0 + acol]);
        As[acol + 0][arow] = a4.x; As[acol + 1][arow] = a4.y;
        As[acol + 2][arow] = a4.z; As[acol + 3][arow] = a4.w;
        float4 b4 = *reinterpret_cast<const float4*>(
            &Bm[(size_t)(k0 + brow) * N + n0 + bcol]);
        *reinterpret_cast<float4*>(&Bs[brow][bcol]) = b4;
        __syncthreads();
#pragma unroll
        for (int k = 0; k < 8; ++k) {
            float af[8], bf[8];
#pragma unroll
            for (int i = 0; i < 8; ++i) af[i] = As[k][ty * 8 + i];
#pragma unroll
            for (int j = 0; j < 8; ++j) bf[j] = Bs[k][txx * 8 + j];
#pragma unroll
            for (int i = 0; i < 8; ++i)
#pragma unroll
                for (int j = 0; j < 8; ++j) acc[i][j] = fmaf(af[i], bf[j], acc[i][j]);
        }
        __syncthreads();
    }
#pragma unroll
    for (int i = 0; i < 8; ++i) {
        int m = m0 + ty * 8 + i;
#pragma unroll
        for (int j = 0; j < 8; ++j) {
            int n = n0 + txx * 8 + j;
            float c = acc[i][j] + (bias ? bias[n] : 0.f);
            if (relu) c = fmaxf(c, 0.f);
            C[(size_t)m * N + n] = c;
        }
    }
}

// ---------------- persistent decoder ----------------------------------------
__global__ __launch_bounds__(NTH) void dec_main_kernel(
    const float* __restrict__ memory,
    const float* __restrict__ bi0, const float* __restrict__ br0,
    const float* __restrict__ bi1, const float* __restrict__ br1,
    const float* __restrict__ v,   const float* __restrict__ bo,
    float* __restrict__ out)
{
    const int cta  = blockIdx.x;
    const int tid  = threadIdx.x;
    const int warp = tid >> 5, lane = tid & 31;
    const int d0   = cta * 2;
    unsigned ep = 0;

    // -------- SMEM-resident weight slices (loaded once, live all 400 steps)
    __shared__ float s_k0[3 * 2 * CIN];   // [(g*2+ds)*CIN + k]
    __shared__ float s_r0[3 * 2 * DD];
    __shared__ float s_k1[3 * 2 * DD];
    __shared__ float s_r1[3 * 2 * DD];
    __shared__ float s_wa[2 * 2 * DD];    // [ds*512 + k]
    __shared__ float s_wo[4 * DD];        // 4 Wo rows (cta<100)
    __shared__ float s_q[DD];
    __shared__ float s_sc[DD];
    __shared__ float s_v[DD];
    __shared__ float s_cx[2 * DD];
    __shared__ float s_red[16];
    __shared__ float s_red2[8];

    for (int i = tid; i < 3 * 2 * CIN; i += NTH) {
        int g = i / (2 * CIN); int rem = i - g * 2 * CIN;
        int ds = rem / CIN;    int k = rem - ds * CIN;
        s_k0[i] = g_k0T[(g * DD + d0 + ds) * CIN + k];
    }
    for (int i = tid; i < 3 * 2 * DD; i += NTH) {
        int g = i / (2 * DD); int rem = i - g * 2 * DD;
        int ds = rem / DD;    int k = rem - ds * DD;
        s_r0[i] = g_r0T[(g * DD + d0 + ds) * DD + k];
        s_k1[i] = g_k1T[(g * DD + d0 + ds) * DD + k];
        s_r1[i] = g_r1T[(g * DD + d0 + ds) * DD + k];
    }
    for (int i = tid; i < 2 * 2 * DD; i += NTH) {
        int ds = i / (2 * DD); int k = i - ds * 2 * DD;
        s_wa[i] = g_WaT[(d0 + ds) * 2 * DD + k];
    }
    if (cta < 100) {
        for (int i = tid; i < 4 * DD; i += NTH) {
            int jj = i / DD; int k = i - jj * DD;
            s_wo[i] = g_WoT[(cta * 4 + jj) * DD + k];
        }
    }
    for (int i = tid; i < DD; i += NTH) s_v[i] = v[i];
    __syncthreads();

    for (int step = 0; step < TDEC; ++step) {
        const int par = step & 1;
        const float* h0c  = g_h0[par];    float* h0n  = g_h0[par ^ 1];
        const float* h1c  = g_h1[par];    float* h1n  = g_h1[par ^ 1];
        const float* attc = g_att[par];   float* attn_ = g_att[par ^ 1];

        // ============ P1: GRU0  (+ output dense for step-1) =================
        {
            const int ds = warp & 1, d = d0 + ds, bg = warp >> 1;
            float wz[12], wr[12], wh[12];
#pragma unroll
            for (int k = 0; k < 12; ++k) {
                wz[k] = s_k0[(0 * 2 + ds) * CIN + k * 32 + lane];
                wr[k] = s_k0[(1 * 2 + ds) * CIN + k * 32 + lane];
                wh[k] = s_k0[(2 * 2 + ds) * CIN + k * 32 + lane];
            }
            float uz[8], ur[8], uh[8];
#pragma unroll
            for (int k = 0; k < 8; ++k) {
                uz[k] = s_r0[(0 * 2 + ds) * DD + k * 32 + lane];
                ur[k] = s_r0[(1 * 2 + ds) * DD + k * 32 + lane];
                uh[k] = s_r0[(2 * 2 + ds) * DD + k * 32 + lane];
            }
            const float biz = bi0[d], bir = bi0[DD + d], bih = bi0[2 * DD + d];
            const float brz = br0[d], brr = br0[DD + d], brh = br0[2 * DD + d];
#pragma unroll 2
            for (int bi = 0; bi < 8; ++bi) {
                int b = bg * 8 + bi;
                const float* pb = &g_p[(b * TDEC + step) * PRE];
                const float* ab = &attc[b * DD];
                const float* hb = &h0c[b * DD];
                float az = 0, ar = 0, ah = 0, gz = 0, gr = 0, gh = 0;
#pragma unroll
                for (int k = 0; k < 4; ++k) {
                    float x = pb[k * 32 + lane];
                    az = fmaf(x, wz[k], az); ar = fmaf(x, wr[k], ar); ah = fmaf(x, wh[k], ah);
                }
#pragma unroll
                for (int k = 0; k < 8; ++k) {
                    float x = ab[k * 32 + lane];
                    az = fmaf(x, wz[4 + k], az); ar = fmaf(x, wr[4 + k], ar); ah = fmaf(x, wh[4 + k], ah);
                    float h = hb[k * 32 + lane];
                    gz = fmaf(h, uz[k], gz); gr = fmaf(h, ur[k], gr); gh = fmaf(h, uh[k], gh);
                }
#pragma unroll
                for (int off = 16; off; off >>= 1) {
                    az += __shfl_xor_sync(0xffffffffu, az, off);
                    ar += __shfl_xor_sync(0xffffffffu, ar, off);
                    ah += __shfl_xor_sync(0xffffffffu, ah, off);
                    gz += __shfl_xor_sync(0xffffffffu, gz, off);
                    gr += __shfl_xor_sync(0xffffffffu, gr, off);
                    gh += __shfl_xor_sync(0xffffffffu, gh, off);
                }
                if (lane == 0) {
                    float z = sigm_f(az + gz + biz + brz);
                    float r = sigm_f(ar + gr + bir + brr);
                    float hc = tanh_f(ah + bih + r * (gh + brh));
                    h0n[b * DD + d] = z * hb[d] + (1.0f - z) * hc;
                }
            }
            if (cta < 100 && step > 0) {
                const int jj = warp & 3, j = cta * 4 + jj, bg2 = warp >> 2;
                float wo[8];
#pragma unroll
                for (int k = 0; k < 8; ++k) wo[k] = s_wo[jj * DD + k * 32 + lane];
                const float boj = bo[j];
#pragma unroll 2
                for (int bi = 0; bi < 16; ++bi) {
                    int b = bg2 * 16 + bi;
                    const float* arow = &attc[b * DD];
                    float a = 0;
#pragma unroll
                    for (int k = 0; k < 8; ++k) a = fmaf(arow[k * 32 + lane], wo[k], a);
                    a = warp_sum_f(a);
                    if (lane == 0)
                        out[(size_t)(b * TDEC + (step - 1)) * ODIM + j] = a + boj;
                }
            }
        }
        grid_sync(++ep);

        // ============ P2: GRU1 ==============================================
        {
            const int ds = warp & 1, d = d0 + ds, bg = warp >> 1;
            float wz[8], wr[8], wh[8], uz[8], ur[8], uh[8];
#pragma unroll
            for (int k = 0; k < 8; ++k) {
                wz[k] = s_k1[(0 * 2 + ds) * DD + k * 32 + lane];
                wr[k] = s_k1[(1 * 2 + ds) * DD + k * 32 + lane];
                wh[k] = s_k1[(2 * 2 + ds) * DD + k * 32 + lane];
                uz[k] = s_r1[(0 * 2 + ds) * DD + k * 32 + lane];
                ur[k] = s_r1[(1 * 2 + ds) * DD + k * 32 + lane];
                uh[k] = s_r1[(2 * 2 + ds) * DD + k * 32 + lane];
            }
            const float biz = bi1[d], bir = bi1[DD + d], bih = bi1[2 * DD + d];
            const float brz = br1[d], brr = br1[DD + d], brh = br1[2 * DD + d];
#pragma unroll 2
            for (int bi = 0; bi < 8; ++bi) {
                int b = bg * 8 + bi;
                const float* xb = &h0n[b * DD];
                const float* hb = &h1c[b * DD];
                float az = 0, ar = 0, ah = 0, gz = 0, gr = 0, gh = 0;
#pragma unroll
                for (int k = 0; k < 8; ++k) {
                    float x = xb[k * 32 + lane];
                    az = fmaf(x, wz[k], az); ar = fmaf(x, wr[k], ar); ah = fmaf(x, wh[k], ah);
                    float h = hb[k * 32 + lane];
                    gz = fmaf(h, uz[k], gz); gr = fmaf(h, ur[k], gr); gh = fmaf(h, uh[k], gh);
                }
#pragma unroll
                for (int off = 16; off; off >>= 1) {
                    az += __shfl_xor_sync(0xffffffffu, az, off);
                    ar += __shfl_xor_sync(0xffffffffu, ar, off);
                    ah += __shfl_xor_sync(0xffffffffu, ah, off);
                    gz += __shfl_xor_sync(0xffffffffu, gz, off);
                    gr += __shfl_xor_sync(0xffffffffu, gr, off);
                    gh += __shfl_xor_sync(0xffffffffu, gh, off);
                }
                if (lane == 0) {
                    float z = sigm_f(az + gz + biz + brz);
                    float r = sigm_f(ar + gr + bir + brr);
                    float hc = tanh_f(ah + bih + r * (gh + brh));
                    h1n[b * DD + d] = z * hb[d] + (1.0f - z) * hc;
                }
            }
        }
        grid_sync(++ep);

        // ============ P3: query (half) + scores + softmax + partial ctx =====
        {
            const int b = cta >> 1, half = cta & 1;
            const int tbase = half * 256;
            // --- query: this CTA computes q[b][half*128 .. +128)
            {
                const float* hb = &h1n[b * DD];
                float hreg[8];
#pragma unroll
                for (int k = 0; k < 8; ++k) hreg[k] = hb[k * 32 + lane];
#pragma unroll 2
                for (int qi = 0; qi < 8; ++qi) {
                    int d = half * 128 + warp * 8 + qi;
                    const float* wr = &g_WqT[d * DD];
                    float a = 0;
#pragma unroll
                    for (int k = 0; k < 8; ++k) a = fmaf(hreg[k], wr[k * 32 + lane], a);
                    a = warp_sum_f(a);
                    if (lane == 0) { g_q[b * DD + d] = a; s_q[d] = a; }
                }
            }
            __syncthreads();
            // pair sync #1: q halves exchanged
            if (tid == 0) {
                __threadfence();
                atomicAdd(&g_pairCnt[b], 1u);
                unsigned tgt = 4u * (unsigned)step + 2u;
                while (*(volatile unsigned*)&g_pairCnt[b] < tgt) { }
                __threadfence();
            }
            __syncthreads();
            if (tid < 128) {
                int oh = half ^ 1;
                s_q[oh * 128 + tid] = g_q[b * DD + oh * 128 + tid];
            }
            __syncthreads();
            // --- scores for this t-half
            float vreg[8], qreg[8];
#pragma unroll
            for (int k = 0; k < 8; ++k) {
                vreg[k] = s_v[k * 32 + lane];
                qreg[k] = s_q[k * 32 + lane];
            }
            float wmax = -1e30f;
#pragma unroll 2
            for (int ti = 0; ti < 16; ++ti) {
                int tt = warp * 16 + ti;
                const float* krow = &g_keys[(size_t)(b * TENC + tbase + tt) * DD];
                float a = 0;
#pragma unroll
                for (int k = 0; k < 8; ++k)
                    a = fmaf(tanh_f(krow[k * 32 + lane] + qreg[k]), vreg[k], a);
                a = warp_sum_f(a);
                if (lane == 0) s_sc[tt] = a;
                wmax = fmaxf(wmax, a);
            }
            if (lane == 0) s_red[warp] = wmax;
            __syncthreads();
            float m_h = s_red[0];
#pragma unroll
            for (int i = 1; i < 16; ++i) m_h = fmaxf(m_h, s_red[i]);
            float ev = (tid < 256) ? __expf(s_sc[tid] - m_h) : 0.f;
            float lw = warp_sum_f(ev);
            if (lane == 0 && warp < 8) s_red2[warp] = lw;
            __syncthreads();
            // pair sync #2: (m,l) exchanged
            if (tid == 0) {
                float l_h = 0;
#pragma unroll
                for (int i = 0; i < 8; ++i) l_h += s_red2[i];
                g_ml[(b * 2 + half) * 2 + 0] = m_h;
                g_ml[(b * 2 + half) * 2 + 1] = l_h;
                __threadfence();
                atomicAdd(&g_pairCnt[b], 1u);
                unsigned tgt = 4u * (unsigned)step + 4u;
                while (*(volatile unsigned*)&g_pairCnt[b] < tgt) { }
                __threadfence();
            }
            __syncthreads();
            float m0v = g_ml[(b * 2 + 0) * 2 + 0], l0v = g_ml[(b * 2 + 0) * 2 + 1];
            float m1v = g_ml[(b * 2 + 1) * 2 + 0], l1v = g_ml[(b * 2 + 1) * 2 + 1];
            float m = fmaxf(m0v, m1v);
            float l = l0v * __expf(m0v - m) + l1v * __expf(m1v - m);
            float inv_l = __fdividef(1.0f, l);
            if (tid < 256) s_sc[tid] = __expf(s_sc[tid] - m) * inv_l;
            __syncthreads();
            // --- partial ctx: 512 threads = (2 t-groups) x (256 d)
            {
                int dd2 = tid & 255, tg = tid >> 8;
                const float* mb = &memory[(size_t)(b * TENC + tbase + tg * 128) * DD + dd2];
                float acc = 0;
#pragma unroll 8
                for (int t = 0; t < 128; ++t)
                    acc = fmaf(s_sc[tg * 128 + t], mb[(size_t)t * DD], acc);
                s_cx[tid] = acc;
            }
            __syncthreads();
            if (tid < 256)
                g_ctxpart[(b * 2 + half) * DD + tid] = s_cx[tid] + s_cx[tid + 256];
        }
        grid_sync(++ep);

        // ============ P4: attention dense ===================================
        {
            const int ds = warp & 1, d = d0 + ds, bg = warp >> 1;
            float wa1[8], wa2[8];
#pragma unroll
            for (int k = 0; k < 8; ++k) {
                wa1[k] = s_wa[ds * 2 * DD + k * 32 + lane];
                wa2[k] = s_wa[ds * 2 * DD + DD + k * 32 + lane];
            }
#pragma unroll 2
            for (int bi = 0; bi < 8; ++bi) {
                int b = bg * 8 + bi;
                const float* hb = &h1n[b * DD];
                const float* c0 = &g_ctxpart[(b * 2 + 0) * DD];
                const float* c1 = &g_ctxpart[(b * 2 + 1) * DD];
                float a = 0;
#pragma unroll
                for (int k = 0; k < 8; ++k) a = fmaf(hb[k * 32 + lane], wa1[k], a);
#pragma unroll
                for (int k = 0; k < 8; ++k) {
                    int i = k * 32 + lane;
                    a = fmaf(c0[i] + c1[i], wa2[k], a);
                }
                a = warp_sum_f(a);
                if (lane == 0) attn_[b * DD + d] = a;
            }
        }
        grid_sync(++ep);
    }

    // final output row (step 399's attn lives in g_att[0])
    if (cta < 100) {
        const float* attc = g_att[0];
        const int jj = warp & 3, j = cta * 4 + jj, bg2 = warp >> 2;
        float wo[8];
#pragma unroll
        for (int k = 0; k < 8; ++k) wo[k] = s_wo[jj * DD + k * 32 + lane];
        const float boj = bo[j];
        for (int bi = 0; bi < 16; ++bi) {
            int b = bg2 * 16 + bi;
            const float* arow = &attc[b * DD];
            float a = 0;
#pragma unroll
            for (int k = 0; k < 8; ++k) a = fmaf(arow[k * 32 + lane], wo[k], a);
            a = warp_sum_f(a);
            if (lane == 0)
                out[(size_t)(b * TDEC + (TDEC - 1)) * ODIM + j] = a + boj;
        }
    }
}

// ---------------- launch -----------------------------------------------------
extern "C" void kernel_launch(void* const* d_in, const int* in_sizes, int n_in,
                              void* d_out, int out_size) {
    (void)in_sizes; (void)n_in; (void)out_size;
    const float* dec    = (const float*)d_in[0];
    const float* memory = (const float*)d_in[1];
    const float* W1  = (const float*)d_in[2];
    const float* b1  = (const float*)d_in[3];
    const float* W2  = (const float*)d_in[4];
    const float* b2  = (const float*)d_in[5];
    const float* k0  = (const float*)d_in[6];
    const float* r0  = (const float*)d_in[7];
    const float* bi0 = (const float*)d_in[8];
    const float* br0 = (const float*)d_in[9];
    const float* k1  = (const float*)d_in[10];
    const float* r1  = (const float*)d_in[11];
    const float* bi1 = (const float*)d_in[12];
    const float* br1 = (const float*)d_in[13];
    const float* Wq  = (const float*)d_in[14];
    const float* Wm  = (const float*)d_in[15];
    const float* v   = (const float*)d_in[16];
    const float* Wa  = (const float*)d_in[17];
    const float* Wo  = (const float*)d_in[18];
    const float* bo  = (const float*)d_in[19];
    float* out = (float*)d_out;

    float *pPre1, *pP, *pKeys, *pk0T, *pr0T, *pk1T, *pr1T, *pWqT, *pWaT, *pWoT;
    cudaGetSymbolAddress((void**)&pPre1, g_pre1);
    cudaGetSymbolAddress((void**)&pP,    g_p);
    cudaGetSymbolAddress((void**)&pKeys, g_keys);
    cudaGetSymbolAddress((void**)&pk0T,  g_k0T);
    cudaGetSymbolAddress((void**)&pr0T,  g_r0T);
    cudaGetSymbolAddress((void**)&pk1T,  g_k1T);
    cudaGetSymbolAddress((void**)&pr1T,  g_r1T);
    cudaGetSymbolAddress((void**)&pWqT,  g_WqT);
    cudaGetSymbolAddress((void**)&pWaT,  g_WaT);
    cudaGetSymbolAddress((void**)&pWoT,  g_WoT);

    dec_init_kernel<<<64, 256>>>();

    auto tr = [](const float* s, float* d, int R, int C) {
        dec_transpose_kernel<<<(R * C + 255) / 256, 256>>>(s, d, R, C);
    };
    tr(k0, pk0T, CIN, 3 * DD);
    tr(r0, pr0T, DD, 3 * DD);
    tr(k1, pk1T, DD, 3 * DD);
    tr(r1, pr1T, DD, 3 * DD);
    tr(Wq, pWqT, DD, DD);
    tr(Wa, pWaT, 2 * DD, DD);
    tr(Wo, pWoT, DD, ODIM);

    dec_sgemm_kernel<<<dim3(256 / 128, (BB * TDEC) / 128), 256>>>(
        dec, W1, b1, pPre1, BB * TDEC, DD, ODIM, 1);
    dec_sgemm_kernel<<<dim3(128 / 128, (BB * TDEC) / 128), 256>>>(
        pPre1, W2, b2, pP, BB * TDEC, PRE, DD, 1);
    dec_sgemm_kernel<<<dim3(256 / 128, (BB * TENC) / 128), 256>>>(
        memory, Wm, nullptr, pKeys, BB * TENC, DD, DD, 0);

    dec_main_kernel<<<GRID, NTH>>>(memory, bi0, br0, bi1, br1, v, bo, out);
}

// round 7
// speedup vs baseline: 2.7173x; 1.0005x over previous
#include <cuda_runtime.h>
#include <cstdint>
#include <cstddef>

#define BB   64
#define TDEC 400
#define TENC 512
#define DD   256
#define PRE  128
#define ODIM 400
#define CIN  (PRE + DD)   // 384
#define GRID 128
#define NTH  512

// ---------------- scratch (device globals; no allocation allowed) ----------
__device__ float g_pre1[BB * TDEC * DD];
__device__ float g_p[BB * TDEC * PRE];
__device__ float g_keys[BB * TENC * DD];
__device__ float g_k0T[3 * DD * CIN];
__device__ float g_r0T[3 * DD * DD];
__device__ float g_k1T[3 * DD * DD];
__device__ float g_r1T[3 * DD * DD];
__device__ float g_WqT[DD * DD];
__device__ float g_WaT[DD * 2 * DD];
__device__ float g_WoT[ODIM * DD];
__device__ float g_h0[2][BB * DD];
__device__ float g_h1[2][BB * DD];
__device__ float g_att[2][BB * DD];
__device__ float g_q[BB * DD];
__device__ float g_ctxpart[BB * 2 * DD];
__device__ float g_ml[BB * 2 * 2];
__device__ unsigned g_barArrive;
__device__ unsigned g_pairCnt[BB];

// ---------------- helpers ---------------------------------------------------
__device__ __forceinline__ float warp_sum_f(float v) {
#pragma unroll
    for (int o = 16; o; o >>= 1) v += __shfl_xor_sync(0xffffffffu, v, o);
    return v;
}
__device__ __forceinline__ float sigm_f(float x) {
    return 1.0f / (1.0f + __expf(-x));
}
__device__ __forceinline__ float tanh_f(float x) {
    float e = __expf(2.0f * x);
    return 1.0f - __fdividef(2.0f, e + 1.0f);
}
__device__ __forceinline__ void grid_sync(unsigned epoch) {
    __syncthreads();
    if (threadIdx.x == 0) {
        __threadfence();
        atomicAdd(&g_barArrive, 1u);
        unsigned tgt = epoch * (unsigned)GRID;
        while (*(volatile unsigned*)&g_barArrive < tgt) { }
        __threadfence();
    }
    __syncthreads();
}

// ---------------- init ------------------------------------------------------
__global__ void dec_init_kernel() {
    int tid = blockIdx.x * blockDim.x + threadIdx.x;
    if (tid == 0) g_barArrive = 0;
    if (tid < BB) g_pairCnt[tid] = 0;
    for (int i = tid; i < BB * DD; i += gridDim.x * blockDim.x) {
        g_h0[0][i] = 0.f; g_h1[0][i] = 0.f; g_att[0][i] = 0.f;
    }
}

// ---------------- transpose [R,C] -> [C,R] ----------------------------------
__global__ void dec_transpose_kernel(const float* __restrict__ src,
                                     float* __restrict__ dst, int R, int C) {
    int idx = blockIdx.x * blockDim.x + threadIdx.x;
    if (idx < R * C) {
        int r = idx / C, c = idx - r * C;
        dst[c * R + r] = src[idx];
    }
}

// ---------------- fp32 SGEMM 128x128x8, TM=TN=8 -----------------------------
__global__ __launch_bounds__(256) void dec_sgemm_kernel(
    const float* __restrict__ A, const float* __restrict__ Bm,
    const float* __restrict__ bias, float* __restrict__ C,
    int M, int N, int K, int relu)
{
    __shared__ float As[8][128];
    __shared__ float Bs[8][128];
    const int tid = threadIdx.x;
    const int m0 = blockIdx.y * 128;
    const int n0 = blockIdx.x * 128;
    const int ty = tid / 16;
    const int txx = tid & 15;
    const int arow = tid >> 1;
    const int acol = (tid & 1) * 4;
    const int brow = tid >> 5;
    const int bcol = (tid & 31) * 4;
    float acc[8][8];
#pragma unroll
    for (int i = 0; i < 8; ++i)
#pragma unroll
        for (int j = 0; j < 8; ++j) acc[i][j] = 0.f;

    for (int k0 = 0; k0 < K; k0 += 8) {
        float4 a4 = *reinterpret_cast<const float4*>(
            &A[(size_t)(m0 + arow) * K + k0 + acol]);
        As[acol + 0][arow] = a4.x; As[acol + 1][arow] = a4.y;
        As[acol + 2][arow] = a4.z; As[acol + 3][arow] = a4.w;
        float4 b4 = *reinterpret_cast<const float4*>(
            &Bm[(size_t)(k0 + brow) * N + n0 + bcol]);
        *reinterpret_cast<float4*>(&Bs[brow][bcol]) = b4;
        __syncthreads();
#pragma unroll
        for (int k = 0; k < 8; ++k) {
            float af[8], bf[8];
#pragma unroll
            for (int i = 0; i < 8; ++i) af[i] = As[k][ty * 8 + i];
#pragma unroll
            for (int j = 0; j < 8; ++j) bf[j] = Bs[k][txx * 8 + j];
#pragma unroll
            for (int i = 0; i < 8; ++i)
#pragma unroll
                for (int j = 0; j < 8; ++j) acc[i][j] = fmaf(af[i], bf[j], acc[i][j]);
        }
        __syncthreads();
    }
#pragma unroll
    for (int i = 0; i < 8; ++i) {
        int m = m0 + ty * 8 + i;
#pragma unroll
        for (int j = 0; j < 8; ++j) {
            int n = n0 + txx * 8 + j;
            float c = acc[i][j] + (bias ? bias[n] : 0.f);
            if (relu) c = fmaxf(c, 0.f);
            C[(size_t)m * N + n] = c;
        }
    }
}

// ---------------- persistent decoder ----------------------------------------
__global__ __launch_bounds__(NTH) void dec_main_kernel(
    const float* __restrict__ memory,
    const float* __restrict__ bi0, const float* __restrict__ br0,
    const float* __restrict__ bi1, const float* __restrict__ br1,
    const float* __restrict__ v,   const float* __restrict__ bo,
    float* __restrict__ out)
{
    const int cta  = blockIdx.x;
    const int tid  = threadIdx.x;
    const int warp = tid >> 5, lane = tid & 31;
    const int d0   = cta * 2;
    unsigned ep = 0;

    // -------- SMEM-resident weight slices (loaded once, live all 400 steps)
    __shared__ float s_k0[3 * 2 * CIN];   // [(g*2+ds)*CIN + k]
    __shared__ float s_r0[3 * 2 * DD];
    __shared__ float s_k1[3 * 2 * DD];
    __shared__ float s_r1[3 * 2 * DD];
    __shared__ float s_wa[2 * 2 * DD];    // [ds*512 + k]
    __shared__ float s_wo[4 * DD];        // 4 Wo rows (cta<100)
    __shared__ float s_q[DD];
    __shared__ float s_sc[DD];
    __shared__ float s_v[DD];
    __shared__ float s_cx[2 * DD];
    __shared__ float s_red[16];
    __shared__ float s_red2[8];

    for (int i = tid; i < 3 * 2 * CIN; i += NTH) {
        int g = i / (2 * CIN); int rem = i - g * 2 * CIN;
        int ds = rem / CIN;    int k = rem - ds * CIN;
        s_k0[i] = g_k0T[(g * DD + d0 + ds) * CIN + k];
    }
    for (int i = tid; i < 3 * 2 * DD; i += NTH) {
        int g = i / (2 * DD); int rem = i - g * 2 * DD;
        int ds = rem / DD;    int k = rem - ds * DD;
        s_r0[i] = g_r0T[(g * DD + d0 + ds) * DD + k];
        s_k1[i] = g_k1T[(g * DD + d0 + ds) * DD + k];
        s_r1[i] = g_r1T[(g * DD + d0 + ds) * DD + k];
    }
    for (int i = tid; i < 2 * 2 * DD; i += NTH) {
        int ds = i / (2 * DD); int k = i - ds * 2 * DD;
        s_wa[i] = g_WaT[(d0 + ds) * 2 * DD + k];
    }
    if (cta < 100) {
        for (int i = tid; i < 4 * DD; i += NTH) {
            int jj = i / DD; int k = i - jj * DD;
            s_wo[i] = g_WoT[(cta * 4 + jj) * DD + k];
        }
    }
    for (int i = tid; i < DD; i += NTH) s_v[i] = v[i];
    __syncthreads();

    for (int step = 0; step < TDEC; ++step) {
        const int par = step & 1;
        const float* h0c  = g_h0[par];    float* h0n  = g_h0[par ^ 1];
        const float* h1c  = g_h1[par];    float* h1n  = g_h1[par ^ 1];
        const float* attc = g_att[par];   float* attn_ = g_att[par ^ 1];

        // ============ P1: GRU0  (+ output dense for step-1) =================
        {
            const int ds = warp & 1, d = d0 + ds, bg = warp >> 1;
            float wz[12], wr[12], wh[12];
#pragma unroll
            for (int k = 0; k < 12; ++k) {
                wz[k] = s_k0[(0 * 2 + ds) * CIN + k * 32 + lane];
                wr[k] = s_k0[(1 * 2 + ds) * CIN + k * 32 + lane];
                wh[k] = s_k0[(2 * 2 + ds) * CIN + k * 32 + lane];
            }
            float uz[8], ur[8], uh[8];
#pragma unroll
            for (int k = 0; k < 8; ++k) {
                uz[k] = s_r0[(0 * 2 + ds) * DD + k * 32 + lane];
                ur[k] = s_r0[(1 * 2 + ds) * DD + k * 32 + lane];
                uh[k] = s_r0[(2 * 2 + ds) * DD + k * 32 + lane];
            }
            const float biz = bi0[d], bir = bi0[DD + d], bih = bi0[2 * DD + d];
            const float brz = br0[d], brr = br0[DD + d], brh = br0[2 * DD + d];
#pragma unroll 2
            for (int bi = 0; bi < 8; ++bi) {
                int b = bg * 8 + bi;
                const float* pb = &g_p[(b * TDEC + step) * PRE];
                const float* ab = &attc[b * DD];
                const float* hb = &h0c[b * DD];
                float az = 0, ar = 0, ah = 0, gz = 0, gr = 0, gh = 0;
#pragma unroll
                for (int k = 0; k < 4; ++k) {
                    float x = pb[k * 32 + lane];
                    az = fmaf(x, wz[k], az); ar = fmaf(x, wr[k], ar); ah = fmaf(x, wh[k], ah);
                }
#pragma unroll
                for (int k = 0; k < 8; ++k) {
                    float x = ab[k * 32 + lane];
                    az = fmaf(x, wz[4 + k], az); ar = fmaf(x, wr[4 + k], ar); ah = fmaf(x, wh[4 + k], ah);
                    float h = hb[k * 32 + lane];
                    gz = fmaf(h, uz[k], gz); gr = fmaf(h, ur[k], gr); gh = fmaf(h, uh[k], gh);
                }
#pragma unroll
                for (int off = 16; off; off >>= 1) {
                    az += __shfl_xor_sync(0xffffffffu, az, off);
                    ar += __shfl_xor_sync(0xffffffffu, ar, off);
                    ah += __shfl_xor_sync(0xffffffffu, ah, off);
                    gz += __shfl_xor_sync(0xffffffffu, gz, off);
                    gr += __shfl_xor_sync(0xffffffffu, gr, off);
                    gh += __shfl_xor_sync(0xffffffffu, gh, off);
                }
                if (lane == 0) {
                    float z = sigm_f(az + gz + biz + brz);
                    float r = sigm_f(ar + gr + bir + brr);
                    float hc = tanh_f(ah + bih + r * (gh + brh));
                    h0n[b * DD + d] = z * hb[d] + (1.0f - z) * hc;
                }
            }
            if (cta < 100 && step > 0) {
                const int jj = warp & 3, j = cta * 4 + jj, bg2 = warp >> 2;
                float wo[8];
#pragma unroll
                for (int k = 0; k < 8; ++k) wo[k] = s_wo[jj * DD + k * 32 + lane];
                const float boj = bo[j];
#pragma unroll 2
                for (int bi = 0; bi < 16; ++bi) {
                    int b = bg2 * 16 + bi;
                    const float* arow = &attc[b * DD];
                    float a = 0;
#pragma unroll
                    for (int k = 0; k < 8; ++k) a = fmaf(arow[k * 32 + lane], wo[k], a);
                    a = warp_sum_f(a);
                    if (lane == 0)
                        out[(size_t)(b * TDEC + (step - 1)) * ODIM + j] = a + boj;
                }
            }
        }
        grid_sync(++ep);

        // ============ P2: GRU1 ==============================================
        {
            const int ds = warp & 1, d = d0 + ds, bg = warp >> 1;
            float wz[8], wr[8], wh[8], uz[8], ur[8], uh[8];
#pragma unroll
            for (int k = 0; k < 8; ++k) {
                wz[k] = s_k1[(0 * 2 + ds) * DD + k * 32 + lane];
                wr[k] = s_k1[(1 * 2 + ds) * DD + k * 32 + lane];
                wh[k] = s_k1[(2 * 2 + ds) * DD + k * 32 + lane];
                uz[k] = s_r1[(0 * 2 + ds) * DD + k * 32 + lane];
                ur[k] = s_r1[(1 * 2 + ds) * DD + k * 32 + lane];
                uh[k] = s_r1[(2 * 2 + ds) * DD + k * 32 + lane];
            }
            const float biz = bi1[d], bir = bi1[DD + d], bih = bi1[2 * DD + d];
            const float brz = br1[d], brr = br1[DD + d], brh = br1[2 * DD + d];
#pragma unroll 2
            for (int bi = 0; bi < 8; ++bi) {
                int b = bg * 8 + bi;
                const float* xb = &h0n[b * DD];
                const float* hb = &h1c[b * DD];
                float az = 0, ar = 0, ah = 0, gz = 0, gr = 0, gh = 0;
#pragma unroll
                for (int k = 0; k < 8; ++k) {
                    float x = xb[k * 32 + lane];
                    az = fmaf(x, wz[k], az); ar = fmaf(x, wr[k], ar); ah = fmaf(x, wh[k], ah);
                    float h = hb[k * 32 + lane];
                    gz = fmaf(h, uz[k], gz); gr = fmaf(h, ur[k], gr); gh = fmaf(h, uh[k], gh);
                }
#pragma unroll
                for (int off = 16; off; off >>= 1) {
                    az += __shfl_xor_sync(0xffffffffu, az, off);
                    ar += __shfl_xor_sync(0xffffffffu, ar, off);
                    ah += __shfl_xor_sync(0xffffffffu, ah, off);
                    gz += __shfl_xor_sync(0xffffffffu, gz, off);
                    gr += __shfl_xor_sync(0xffffffffu, gr, off);
                    gh += __shfl_xor_sync(0xffffffffu, gh, off);
                }
                if (lane == 0) {
                    float z = sigm_f(az + gz + biz + brz);
                    float r = sigm_f(ar + gr + bir + brr);
                    float hc = tanh_f(ah + bih + r * (gh + brh));
                    h1n[b * DD + d] = z * hb[d] + (1.0f - z) * hc;
                }
            }
        }
        grid_sync(++ep);

        // ============ P3: query (half) + scores + softmax + partial ctx =====
        {
            const int b = cta >> 1, half = cta & 1;
            const int tbase = half * 256;
            // --- query: this CTA computes q[b][half*128 .. +128)
            {
                const float* hb = &h1n[b * DD];
                float hreg[8];
#pragma unroll
                for (int k = 0; k < 8; ++k) hreg[k] = hb[k * 32 + lane];
#pragma unroll 2
                for (int qi = 0; qi < 8; ++qi) {
                    int d = half * 128 + warp * 8 + qi;
                    const float* wr = &g_WqT[d * DD];
                    float a = 0;
#pragma unroll
                    for (int k = 0; k < 8; ++k) a = fmaf(hreg[k], wr[k * 32 + lane], a);
                    a = warp_sum_f(a);
                    if (lane == 0) { g_q[b * DD + d] = a; s_q[d] = a; }
                }
            }
            __syncthreads();
            // pair sync #1: q halves exchanged
            if (tid == 0) {
                __threadfence();
                atomicAdd(&g_pairCnt[b], 1u);
                unsigned tgt = 4u * (unsigned)step + 2u;
                while (*(volatile unsigned*)&g_pairCnt[b] < tgt) { }
                __threadfence();
            }
            __syncthreads();
            if (tid < 128) {
                int oh = half ^ 1;
                s_q[oh * 128 + tid] = g_q[b * DD + oh * 128 + tid];
            }
            __syncthreads();
            // --- scores for this t-half
            float vreg[8], qreg[8];
#pragma unroll
            for (int k = 0; k < 8; ++k) {
                vreg[k] = s_v[k * 32 + lane];
                qreg[k] = s_q[k * 32 + lane];
            }
            float wmax = -1e30f;
#pragma unroll 2
            for (int ti = 0; ti < 16; ++ti) {
                int tt = warp * 16 + ti;
                const float* krow = &g_keys[(size_t)(b * TENC + tbase + tt) * DD];
                float a = 0;
#pragma unroll
                for (int k = 0; k < 8; ++k)
                    a = fmaf(tanh_f(krow[k * 32 + lane] + qreg[k]), vreg[k], a);
                a = warp_sum_f(a);
                if (lane == 0) s_sc[tt] = a;
                wmax = fmaxf(wmax, a);
            }
            if (lane == 0) s_red[warp] = wmax;
            __syncthreads();
            float m_h = s_red[0];
#pragma unroll
            for (int i = 1; i < 16; ++i) m_h = fmaxf(m_h, s_red[i]);
            float ev = (tid < 256) ? __expf(s_sc[tid] - m_h) : 0.f;
            float lw = warp_sum_f(ev);
            if (lane == 0 && warp < 8) s_red2[warp] = lw;
            __syncthreads();
            // pair sync #2: (m,l) exchanged
            if (tid == 0) {
                float l_h = 0;
#pragma unroll
                for (int i = 0; i < 8; ++i) l_h += s_red2[i];
                g_ml[(b * 2 + half) * 2 + 0] = m_h;
                g_ml[(b * 2 + half) * 2 + 1] = l_h;
                __threadfence();
                atomicAdd(&g_pairCnt[b], 1u);
                unsigned tgt = 4u * (unsigned)step + 4u;
                while (*(volatile unsigned*)&g_pairCnt[b] < tgt) { }
                __threadfence();
            }
            __syncthreads();
            float m0v = g_ml[(b * 2 + 0) * 2 + 0], l0v = g_ml[(b * 2 + 0) * 2 + 1];
            float m1v = g_ml[(b * 2 + 1) * 2 + 0], l1v = g_ml[(b * 2 + 1) * 2 + 1];
            float m = fmaxf(m0v, m1v);
            float l = l0v * __expf(m0v - m) + l1v * __expf(m1v - m);
            float inv_l = __fdividef(1.0f, l);
            if (tid < 256) s_sc[tid] = __expf(s_sc[tid] - m) * inv_l;
            __syncthreads();
            // --- partial ctx: 512 threads = (2 t-groups) x (256 d)
            {
                int dd2 = tid & 255, tg = tid >> 8;
                const float* mb = &memory[(size_t)(b * TENC + tbase + tg * 128) * DD + dd2];
                float acc = 0;
#pragma unroll 8
                for (int t = 0; t < 128; ++t)
                    acc = fmaf(s_sc[tg * 128 + t], mb[(size_t)t * DD], acc);
                s_cx[tid] = acc;
            }
            __syncthreads();
            if (tid < 256)
                g_ctxpart[(b * 2 + half) * DD + tid] = s_cx[tid] + s_cx[tid + 256];
        }
        grid_sync(++ep);

        // ============ P4: attention dense ===================================
        {
            const int ds = warp & 1, d = d0 + ds, bg = warp >> 1;
            float wa1[8], wa2[8];
#pragma unroll
            for (int k = 0; k < 8; ++k) {
                wa1[k] = s_wa[ds * 2 * DD + k * 32 + lane];
                wa2[k] = s_wa[ds * 2 * DD + DD + k * 32 + lane];
            }
#pragma unroll 2
            for (int bi = 0; bi < 8; ++bi) {
                int b = bg * 8 + bi;
                const float* hb = &h1n[b * DD];
                const float* c0 = &g_ctxpart[(b * 2 + 0) * DD];
                const float* c1 = &g_ctxpart[(b * 2 + 1) * DD];
                float a = 0;
#pragma unroll
                for (int k = 0; k < 8; ++k) a = fmaf(hb[k * 32 + lane], wa1[k], a);
#pragma unroll
                for (int k = 0; k < 8; ++k) {
                    int i = k * 32 + lane;
                    a = fmaf(c0[i] + c1[i], wa2[k], a);
                }
                a = warp_sum_f(a);
                if (lane == 0) attn_[b * DD + d] = a;
            }
        }
        grid_sync(++ep);
    }

    // final output row (step 399's attn lives in g_att[0])
    if (cta < 100) {
        const float* attc = g_att[0];
        const int jj = warp & 3, j = cta * 4 + jj, bg2 = warp >> 2;
        float wo[8];
#pragma unroll
        for (int k = 0; k < 8; ++k) wo[k] = s_wo[jj * DD + k * 32 + lane];
        const float boj = bo[j];
        for (int bi = 0; bi < 16; ++bi) {
            int b = bg2 * 16 + bi;
            const float* arow = &attc[b * DD];
            float a = 0;
#pragma unroll
            for (int k = 0; k < 8; ++k) a = fmaf(arow[k * 32 + lane], wo[k], a);
            a = warp_sum_f(a);
            if (lane == 0)
                out[(size_t)(b * TDEC + (TDEC - 1)) * ODIM + j] = a + boj;
        }
    }
}

// ---------------- launch -----------------------------------------------------
extern "C" void kernel_launch(void* const* d_in, const int* in_sizes, int n_in,
                              void* d_out, int out_size) {
    (void)in_sizes; (void)n_in; (void)out_size;
    const float* dec    = (const float*)d_in[0];
    const float* memory = (const float*)d_in[1];
    const float* W1  = (const float*)d_in[2];
    const float* b1  = (const float*)d_in[3];
    const float* W2  = (const float*)d_in[4];
    const float* b2  = (const float*)d_in[5];
    const float* k0  = (const float*)d_in[6];
    const float* r0  = (const float*)d_in[7];
    const float* bi0 = (const float*)d_in[8];
    const float* br0 = (const float*)d_in[9];
    const float* k1  = (const float*)d_in[10];
    const float* r1  = (const float*)d_in[11];
    const float* bi1 = (const float*)d_in[12];
    const float* br1 = (const float*)d_in[13];
    const float* Wq  = (const float*)d_in[14];
    const float* Wm  = (const float*)d_in[15];
    const float* v   = (const float*)d_in[16];
    const float* Wa  = (const float*)d_in[17];
    const float* Wo  = (const float*)d_in[18];
    const float* bo  = (const float*)d_in[19];
    float* out = (float*)d_out;

    float *pPre1, *pP, *pKeys, *pk0T, *pr0T, *pk1T, *pr1T, *pWqT, *pWaT, *pWoT;
    cudaGetSymbolAddress((void**)&pPre1, g_pre1);
    cudaGetSymbolAddress((void**)&pP,    g_p);
    cudaGetSymbolAddress((void**)&pKeys, g_keys);
    cudaGetSymbolAddress((void**)&pk0T,  g_k0T);
    cudaGetSymbolAddress((void**)&pr0T,  g_r0T);
    cudaGetSymbolAddress((void**)&pk1T,  g_k1T);
    cudaGetSymbolAddress((void**)&pr1T,  g_r1T);
    cudaGetSymbolAddress((void**)&pWqT,  g_WqT);
    cudaGetSymbolAddress((void**)&pWaT,  g_WaT);
    cudaGetSymbolAddress((void**)&pWoT,  g_WoT);

    dec_init_kernel<<<64, 256>>>();

    auto tr = [](const float* s, float* d, int R, int C) {
        dec_transpose_kernel<<<(R * C + 255) / 256, 256>>>(s, d, R, C);
    };
    tr(k0, pk0T, CIN, 3 * DD);
    tr(r0, pr0T, DD, 3 * DD);
    tr(k1, pk1T, DD, 3 * DD);
    tr(r1, pr1T, DD, 3 * DD);
    tr(Wq, pWqT, DD, DD);
    tr(Wa, pWaT, 2 * DD, DD);
    tr(Wo, pWoT, DD, ODIM);

    dec_sgemm_kernel<<<dim3(256 / 128, (BB * TDEC) / 128), 256>>>(
        dec, W1, b1, pPre1, BB * TDEC, DD, ODIM, 1);
    dec_sgemm_kernel<<<dim3(128 / 128, (BB * TDEC) / 128), 256>>>(
        pPre1, W2, b2, pP, BB * TDEC, PRE, DD, 1);
    dec_sgemm_kernel<<<dim3(256 / 128, (BB * TENC) / 128), 256>>>(
        memory, Wm, nullptr, pKeys, BB * TENC, DD, DD, 0);

    dec_main_kernel<<<GRID, NTH>>>(memory, bi0, br0, bi1, br1, v, bo, out);
}